// round 2
// baseline (speedup 1.0000x reference)
#include <cuda_runtime.h>
#include <cstdint>

// GRU: B=64, T=4096, F=100, H=200, O=1 (flax GRUCell convention)
// One persistent cluster-cooperative kernel. 32 clusters x 4 CTAs (128 CTAs, 1/SM).
// Each cluster owns 2 batch sequences; each CTA owns 50 hidden units (150 gate cols)
// with its Wi/Wh column slice resident in SMEM. h state is exchanged per step via
// DSMEM (st.shared::cluster) and steps are separated by barrier.cluster.

#define Bq      64
#define Tq      4096
#define Fq      100
#define Hq      200
#define G3      600
#define CLUSTER 4
#define BG      2        // batches per cluster
#define JPC     50       // hidden units per CTA
#define CPC     150      // gate-columns per CTA (3 gates * 50)
#define NTHR    320
#define WST     308      // padded row stride (words) for conflict-free LDS.128

struct Smem {
    float W[CPC * WST];            // [col][k]: k<100 -> Wi, k in [100,300) -> Wh   (184800 B)
    float s_in[2][BG][304];        // per parity, per batch: [0:100)=x_t, [100:300)=h (4864 B)
    float gX[NTHR];                // x-part dot results
    float gH[NTHR];                // h-part dot results
    float bi_s[160];               // bi for my 150 cols
    float bhn_s[64];               // bhn for my 50 j
    float Wo_s[64];                // Wo for my 50 j
    float ypar[2][CLUSTER][BG];    // y partials gathered at rank 0 (parity-buffered)
    float ywarp[4];                // per-warp y reduction
};

__device__ __forceinline__ uint32_t smem_u32(const void* p) {
    return (uint32_t)__cvta_generic_to_shared(p);
}

__device__ __forceinline__ void st_cluster_f32(uint32_t laddr, uint32_t rr, float v) {
    uint32_t ra;
    asm volatile("mapa.shared::cluster.u32 %0, %1, %2;" : "=r"(ra) : "r"(laddr), "r"(rr));
    asm volatile("st.shared::cluster.f32 [%0], %1;" :: "r"(ra), "f"(v) : "memory");
}

__device__ __forceinline__ float sigf(float x) {
    // 1/(1+e^-x); __expf(inf)=inf -> rcp gives 0, saturates correctly
    return __fdividef(1.0f, 1.0f + __expf(-x));
}
__device__ __forceinline__ float tanh_fast(float x) {
    return 2.0f * sigf(2.0f * x) - 1.0f;   // saturates correctly at +/-1
}

__global__ void __launch_bounds__(NTHR, 1)
gru_kernel(const float* __restrict__ x,  const float* __restrict__ Wi,
           const float* __restrict__ bi, const float* __restrict__ Wh,
           const float* __restrict__ bhn, const float* __restrict__ Wo,
           const float* __restrict__ bo, float* __restrict__ out)
{
    extern __shared__ char smraw[];
    Smem* sm = reinterpret_cast<Smem*>(smraw);
    const int tid = threadIdx.x;
    uint32_t rank;
    asm("mov.u32 %0, %%cluster_ctarank;" : "=r"(rank));
    const int cid = blockIdx.x >> 2;
    const int b0g = cid * BG;

    // ---- one-time SMEM init ----
    // Weights: W[c][k] with k<100 = Wi[k][gcol], k>=100 = Wh[k-100][gcol]
    for (int idx = tid; idx < CPC * 300; idx += NTHR) {
        int k = idx / CPC, c = idx - k * CPC;
        int g = c / JPC, jj = c - g * JPC;
        int gcol = g * Hq + (int)rank * JPC + jj;
        float w = (k < Fq) ? Wi[(size_t)k * G3 + gcol] : Wh[(size_t)(k - Fq) * G3 + gcol];
        sm->W[c * WST + k] = w;
    }
    for (int i = tid; i < 160; i += NTHR) {
        float v = 0.f;
        if (i < CPC) { int g = i / JPC, jj = i - g * JPC; v = bi[g * Hq + (int)rank * JPC + jj]; }
        sm->bi_s[i] = v;
    }
    if (tid < JPC) {
        sm->bhn_s[tid] = bhn[(int)rank * JPC + tid];
        sm->Wo_s[tid]  = Wo[(int)rank * JPC + tid];
    }
    // zero h region of both parities
    for (int i = tid; i < 2 * BG * Hq; i += NTHR) {
        int p = i / (BG * Hq); int r2 = i - p * BG * Hq;
        int b = r2 / Hq; int k = r2 - b * Hq;
        sm->s_in[p][b][100 + k] = 0.f;
    }
    // stage x for t=0
    const int plb = tid / 160, pf = tid - plb * 160;
    if (pf < Fq) sm->s_in[0][plb][pf] = x[(size_t)(b0g + plb) * (Tq * Fq) + pf];
    const float bo0 = bo[0];

    __syncthreads();
    asm volatile("barrier.cluster.arrive.aligned;" ::: "memory");
    asm volatile("barrier.cluster.wait.aligned;"   ::: "memory");

    const int c  = tid >> 1, lb = tid & 1;   // dot mapping: lanes (b0,b1) adjacent -> W dedup
    const int eb = tid >> 6, jj = tid & 63;  // epilogue mapping
    const int jg = (int)rank * JPC + jj;

    int par = 0;
    for (int t = 0; t < Tq; ++t) {
        const int nxt = par ^ 1;

        // prefetch x_{t+1} into registers (overlaps with dot compute)
        float xr = 0.f;
        const bool hasx = (t + 1 < Tq) && (pf < Fq);
        if (hasx) xr = x[(size_t)(b0g + plb) * (Tq * Fq) + (size_t)(t + 1) * Fq + pf];

        // ---- dot phase: 300 dots of K=300 (x-part kept separate for the n-gate) ----
        if (c < CPC) {
            const float4* wp = reinterpret_cast<const float4*>(&sm->W[c * WST]);
            const float4* vp = reinterpret_cast<const float4*>(&sm->s_in[par][lb][0]);
            float a0 = 0.f, a1 = 0.f;
            #pragma unroll
            for (int q = 0; q < 25; ++q) {
                float4 w = wp[q], v = vp[q];
                a0 = fmaf(w.x, v.x, a0); a1 = fmaf(w.y, v.y, a1);
                a0 = fmaf(w.z, v.z, a0); a1 = fmaf(w.w, v.w, a1);
            }
            float h0 = 0.f, h1 = 0.f;
            #pragma unroll
            for (int q = 25; q < 75; ++q) {
                float4 w = wp[q], v = vp[q];
                h0 = fmaf(w.x, v.x, h0); h1 = fmaf(w.y, v.y, h1);
                h0 = fmaf(w.z, v.z, h0); h1 = fmaf(w.w, v.w, h1);
            }
            sm->gX[tid] = a0 + a1;
            sm->gH[tid] = h0 + h1;
        }
        __syncthreads();

        // ---- epilogue: gates, h update, DSMEM h exchange, y partial ----
        float ycon = 0.f;
        if (tid < 128 && jj < JPC) {
            int i0 = ((0 * JPC + jj) << 1) | eb;
            int i1 = ((1 * JPC + jj) << 1) | eb;
            int i2 = ((2 * JPC + jj) << 1) | eb;
            float ar = sm->gX[i0] + sm->gH[i0] + sm->bi_s[jj];
            float az = sm->gX[i1] + sm->gH[i1] + sm->bi_s[JPC + jj];
            float r  = sigf(ar);
            float z  = sigf(az);
            float pre = sm->gX[i2] + sm->bi_s[2 * JPC + jj] + r * (sm->gH[i2] + sm->bhn_s[jj]);
            float n  = tanh_fast(pre);
            float hold = sm->s_in[par][eb][100 + jg];
            float hnew = n + z * (hold - n);   // (1-z)*n + z*h
            uint32_t la = smem_u32(&sm->s_in[nxt][eb][100 + jg]);
            #pragma unroll
            for (uint32_t rr = 0; rr < CLUSTER; ++rr) st_cluster_f32(la, rr, hnew);
            ycon = hnew * sm->Wo_s[jj];
        }
        if (tid < 128) {
            #pragma unroll
            for (int m = 16; m > 0; m >>= 1) ycon += __shfl_xor_sync(0xffffffffu, ycon, m);
            if ((tid & 31) == 0) sm->ywarp[tid >> 5] = ycon;
        }
        if (hasx) sm->s_in[nxt][plb][pf] = xr;   // local x stage for t+1
        __syncthreads();

        if (tid < BG) {
            float yl = sm->ywarp[2 * tid] + sm->ywarp[2 * tid + 1];
            uint32_t la = smem_u32(&sm->ypar[t & 1][rank][tid]);
            st_cluster_f32(la, 0u, yl);          // partial to rank 0
        }
        asm volatile("barrier.cluster.arrive.aligned;" ::: "memory");
        asm volatile("barrier.cluster.wait.aligned;"   ::: "memory");

        if (rank == 0 && tid < BG) {
            const float* yp = &sm->ypar[t & 1][0][0];
            float y = (yp[0 * BG + tid] + yp[1 * BG + tid])
                    + (yp[2 * BG + tid] + yp[3 * BG + tid]) + bo0;
            out[(size_t)(b0g + tid) * Tq + t] = y;
        }
        par = nxt;
    }
}

extern "C" void kernel_launch(void* const* d_in, const int* in_sizes, int n_in,
                              void* d_out, int out_size) {
    (void)in_sizes; (void)n_in; (void)out_size;
    const float* x   = (const float*)d_in[0];
    const float* Wi  = (const float*)d_in[1];
    const float* bi  = (const float*)d_in[2];
    const float* Wh  = (const float*)d_in[3];
    const float* bhn = (const float*)d_in[4];
    const float* Wo  = (const float*)d_in[5];
    const float* bo  = (const float*)d_in[6];
    float* out = (float*)d_out;

    cudaFuncSetAttribute(gru_kernel, cudaFuncAttributeMaxDynamicSharedMemorySize,
                         (int)sizeof(Smem));

    cudaLaunchConfig_t cfg = {};
    cfg.gridDim  = dim3(128, 1, 1);
    cfg.blockDim = dim3(NTHR, 1, 1);
    cfg.dynamicSmemBytes = sizeof(Smem);
    cfg.stream = 0;
    cudaLaunchAttribute attr[1];
    attr[0].id = cudaLaunchAttributeClusterDimension;
    attr[0].val.clusterDim.x = CLUSTER;
    attr[0].val.clusterDim.y = 1;
    attr[0].val.clusterDim.z = 1;
    cfg.attrs = attr;
    cfg.numAttrs = 1;

    cudaLaunchKernelEx(&cfg, gru_kernel, x, Wi, bi, Wh, bhn, Wo, bo, out);
}